// round 1
// baseline (speedup 1.0000x reference)
#include <cuda_runtime.h>
#include <cstdint>

// Problem constants
#define BATCH   4
#define NSEQ    2048
#define DMODEL  1024
#define KDIM    32
#define ROWS    (BATCH * NSEQ)        // 8192 flattened rows
#define CLAMP_V 10.0f

// Scratch: G [8192][32] (1 MiB) and Gsq [8192] (32 KiB). Static device arrays
// are the sanctioned scratch mechanism (no allocation allowed).
__device__ float g_G[(size_t)ROWS * KDIM];
__device__ float g_Gsq[ROWS];

// ---------------------------------------------------------------------------
// Kernel 1: G = H @ W^T  (8192 x 32 x 1024) + per-row squared norm.
// Block = 256 threads handles 32 rows. d-chunks of 128 staged in smem.
// Thread (row = tid>>3, kg = tid&7) owns 4 k-outputs of one row.
// ---------------------------------------------------------------------------
__global__ void __launch_bounds__(256) k1_proj(
    const float* __restrict__ H, const float* __restrict__ W)
{
    __shared__ float Hs[32][132];   // 132 stride: 16B aligned rows, conflict-free
    __shared__ float Ws[32][132];

    const int tid = threadIdx.x;
    const int r0  = blockIdx.x * 32;
    const int row = tid >> 3;       // 0..31
    const int kg  = tid & 7;        // 0..7
    const int k0  = kg * 4;

    float acc[4] = {0.f, 0.f, 0.f, 0.f};

    for (int dc = 0; dc < DMODEL; dc += 128) {
        // Cooperative load: 32x128 floats each for H-tile and W-tile (float4).
        #pragma unroll
        for (int e = tid * 4; e < 32 * 128; e += 256 * 4) {
            const int rr = e >> 7;
            const int cc = e & 127;
            float4 h4 = *(const float4*)(H + (size_t)(r0 + rr) * DMODEL + dc + cc);
            *(float4*)&Hs[rr][cc] = h4;
            float4 w4 = *(const float4*)(W + (size_t)rr * DMODEL + dc + cc);
            *(float4*)&Ws[rr][cc] = w4;
        }
        __syncthreads();

        #pragma unroll 8
        for (int d4 = 0; d4 < 128; d4 += 4) {
            const float4 h = *(const float4*)&Hs[row][d4];
            #pragma unroll
            for (int kk = 0; kk < 4; kk++) {
                const float4 w = *(const float4*)&Ws[k0 + kk][d4];
                acc[kk] += h.x * w.x;
                acc[kk] += h.y * w.y;
                acc[kk] += h.z * w.z;
                acc[kk] += h.w * w.w;
            }
        }
        __syncthreads();
    }

    float sq = 0.f;
    #pragma unroll
    for (int kk = 0; kk < 4; kk++) {
        g_G[(size_t)(r0 + row) * KDIM + k0 + kk] = acc[kk];
        sq += acc[kk] * acc[kk];
    }
    // Reduce sq across the 8 kg-lanes of this row (lanes row*8 .. row*8+7).
    sq += __shfl_xor_sync(0xffffffffu, sq, 1);
    sq += __shfl_xor_sync(0xffffffffu, sq, 2);
    sq += __shfl_xor_sync(0xffffffffu, sq, 4);
    if (kg == 0) g_Gsq[r0 + row] = sq;
}

// ---------------------------------------------------------------------------
// Kernel 2: per block compute 128(i) x 64(j) tile of
//   B_next = clamp(alpha*B_prev - beta*max(|G_i - G_j|^2, 0), -10, 10)
// gram via k-major smem tiles; 8x4 register tile per thread.
// ---------------------------------------------------------------------------
__global__ void __launch_bounds__(256) k2_bias(
    const float* __restrict__ Bprev,
    const float* __restrict__ alpha_p,
    const float* __restrict__ beta_p,
    float* __restrict__ out)
{
    __shared__ float Gis[KDIM][132];  // k-major, i in [0,128)
    __shared__ float Gjs[KDIM][68];   // k-major, j in [0,64); stride 68 -> 16B aligned
    __shared__ float sqi[128];
    __shared__ float sqj[64];

    const int b   = blockIdx.z;
    const int i0  = blockIdx.y * 128;
    const int j0  = blockIdx.x * 64;
    const int gi0 = b * NSEQ + i0;
    const int gj0 = b * NSEQ + j0;
    const int tid = threadIdx.x;

    const float alpha = *alpha_p;   // uniform scalar loads, issued early
    const float beta  = *beta_p;

    // Load G tiles (global reads coalesced over k), transpose into k-major smem.
    #pragma unroll
    for (int e = tid; e < 128 * KDIM; e += 256) {
        const int i = e >> 5;
        const int k = e & 31;
        Gis[k][i] = g_G[(size_t)(gi0 + i) * KDIM + k];
    }
    #pragma unroll
    for (int e = tid; e < 64 * KDIM; e += 256) {
        const int j = e >> 5;
        const int k = e & 31;
        Gjs[k][j] = g_G[(size_t)(gj0 + j) * KDIM + k];
    }
    if (tid < 128) sqi[tid] = g_Gsq[gi0 + tid];
    if (tid < 64)  sqj[tid] = g_Gsq[gj0 + tid];
    __syncthreads();

    const int ti = tid >> 4;        // 0..15
    const int tj = tid & 15;        // 0..15
    const int ib = ti * 8;
    const int jb = tj * 4;

    float acc[8][4];
    #pragma unroll
    for (int ii = 0; ii < 8; ii++)
        #pragma unroll
        for (int jj = 0; jj < 4; jj++)
            acc[ii][jj] = 0.f;

    #pragma unroll 8
    for (int k = 0; k < KDIM; k++) {
        float gi[8], gj[4];
        *(float4*)&gj[0] = *(const float4*)&Gjs[k][jb];
        *(float4*)&gi[0] = *(const float4*)&Gis[k][ib];
        *(float4*)&gi[4] = *(const float4*)&Gis[k][ib + 4];
        #pragma unroll
        for (int ii = 0; ii < 8; ii++)
            #pragma unroll
            for (int jj = 0; jj < 4; jj++)
                acc[ii][jj] += gi[ii] * gj[jj];
    }

    // Fused epilogue: dist -> EMA -> clamp, float4 traffic.
    const size_t base = ((size_t)b * NSEQ + (i0 + ib)) * NSEQ + (j0 + jb);
    const float* bp = Bprev + base;
    float*       op = out + base;

    #pragma unroll
    for (int ii = 0; ii < 8; ii++) {
        const float4 bv = *(const float4*)(bp + (size_t)ii * NSEQ);
        const float s_i = sqi[ib + ii];
        float4 r;
        {
            float d0 = fmaxf(s_i + sqj[jb + 0] - 2.f * acc[ii][0], 0.f);
            float d1 = fmaxf(s_i + sqj[jb + 1] - 2.f * acc[ii][1], 0.f);
            float d2 = fmaxf(s_i + sqj[jb + 2] - 2.f * acc[ii][2], 0.f);
            float d3 = fmaxf(s_i + sqj[jb + 3] - 2.f * acc[ii][3], 0.f);
            r.x = fminf(fmaxf(alpha * bv.x - beta * d0, -CLAMP_V), CLAMP_V);
            r.y = fminf(fmaxf(alpha * bv.y - beta * d1, -CLAMP_V), CLAMP_V);
            r.z = fminf(fmaxf(alpha * bv.z - beta * d2, -CLAMP_V), CLAMP_V);
            r.w = fminf(fmaxf(alpha * bv.w - beta * d3, -CLAMP_V), CLAMP_V);
        }
        *(float4*)(op + (size_t)ii * NSEQ) = r;
    }
}

// ---------------------------------------------------------------------------
// Launch: inputs per metadata order: H, B_prev, W, alpha, beta. Output fp32.
// ---------------------------------------------------------------------------
extern "C" void kernel_launch(void* const* d_in, const int* in_sizes, int n_in,
                              void* d_out, int out_size)
{
    const float* H     = (const float*)d_in[0];
    const float* Bprev = (const float*)d_in[1];
    const float* W     = (const float*)d_in[2];
    const float* alpha = (const float*)d_in[3];
    const float* beta  = (const float*)d_in[4];
    float* out = (float*)d_out;

    k1_proj<<<ROWS / 32, 256>>>(H, W);

    dim3 g2(NSEQ / 64, NSEQ / 128, BATCH);
    k2_bias<<<g2, 256>>>(Bprev, alpha, beta, out);
}

// round 2
// speedup vs baseline: 2.7999x; 2.7999x over previous
#include <cuda_runtime.h>
#include <cstdint>

#define BATCH   4
#define NSEQ    2048
#define DMODEL  1024
#define KDIM    32
#define ROWS    (BATCH * NSEQ)
#define CLAMP_V 10.0f

// Scratch (static device arrays are the sanctioned scratch mechanism)
__device__ float g_G[(size_t)ROWS * KDIM];
__device__ float g_Gsq[ROWS];

// ---- packed f32x2 helpers (Blackwell FFMA2 path, PTX-only) -----------------
__device__ __forceinline__ unsigned long long pk2(float a, float b) {
    unsigned long long r;
    asm("mov.b64 %0, {%1, %2};" : "=l"(r) : "f"(a), "f"(b));
    return r;
}
__device__ __forceinline__ void unpk2(unsigned long long v, float& a, float& b) {
    asm("mov.b64 {%0, %1}, %2;" : "=f"(a), "=f"(b) : "l"(v));
}
__device__ __forceinline__ unsigned long long fma2(
    unsigned long long a, unsigned long long b, unsigned long long c) {
    unsigned long long d;
    asm("fma.rn.f32x2 %0, %1, %2, %3;" : "=l"(d) : "l"(a), "l"(b), "l"(c));
    return d;
}
__device__ __forceinline__ unsigned long long add2(
    unsigned long long a, unsigned long long b) {
    unsigned long long d;
    asm("add.rn.f32x2 %0, %1, %2;" : "=l"(d) : "l"(a), "l"(b));
    return d;
}
__device__ __forceinline__ unsigned long long mul2(
    unsigned long long a, unsigned long long b) {
    unsigned long long d;
    asm("mul.rn.f32x2 %0, %1, %2;" : "=l"(d) : "l"(a), "l"(b));
    return d;
}

union F4U { float4 f; unsigned long long u[2]; float s[4]; };

// ---------------------------------------------------------------------------
// Kernel 1: G = H @ W^T  (8192 x 32 x 1024) + per-row squared norm.
// 128 threads, block = 32 rows x 32 k. Thread tile: 4 rows x 2 k (k = tj, tj+16).
// d-chunks of 64 double-buffered via registers (prefetch hides DRAM latency).
// ---------------------------------------------------------------------------
__global__ void __launch_bounds__(128) k1_proj(
    const float* __restrict__ H, const float* __restrict__ W)
{
    __shared__ float Hs[2][32][68];   // row-major [row][d], stride 68
    __shared__ float Ws[2][32][68];

    const int tid = threadIdx.x;
    const int r0  = blockIdx.x * 32;
    const int ti  = tid >> 4;         // 0..7 -> rows ti*4 .. ti*4+3
    const int tj  = tid & 15;         // k = tj and tj+16

    float4 hreg[4], wreg[4];

    // Prologue: load chunk 0
    #pragma unroll
    for (int p = 0; p < 4; p++) {
        const int e  = tid + p * 128;
        const int rr = e >> 4;
        const int cc = (e & 15) * 4;
        hreg[p] = *(const float4*)(H + (size_t)(r0 + rr) * DMODEL + cc);
        wreg[p] = *(const float4*)(W + (size_t)rr * DMODEL + cc);
    }
    #pragma unroll
    for (int p = 0; p < 4; p++) {
        const int e  = tid + p * 128;
        const int rr = e >> 4;
        const int cc = (e & 15) * 4;
        *(float4*)&Hs[0][rr][cc] = hreg[p];
        *(float4*)&Ws[0][rr][cc] = wreg[p];
    }
    __syncthreads();

    float acc[4][2];
    #pragma unroll
    for (int r = 0; r < 4; r++) { acc[r][0] = 0.f; acc[r][1] = 0.f; }

    for (int c = 0; c < 16; c++) {
        const int buf = c & 1;

        // Prefetch next chunk into registers (latency overlaps compute below)
        if (c < 15) {
            const int dc = (c + 1) * 64;
            #pragma unroll
            for (int p = 0; p < 4; p++) {
                const int e  = tid + p * 128;
                const int rr = e >> 4;
                const int cc = (e & 15) * 4;
                hreg[p] = *(const float4*)(H + (size_t)(r0 + rr) * DMODEL + dc + cc);
                wreg[p] = *(const float4*)(W + (size_t)rr * DMODEL + dc + cc);
            }
        }

        #pragma unroll 8
        for (int d4 = 0; d4 < 64; d4 += 4) {
            const float4 gj0 = *(const float4*)&Ws[buf][tj][d4];
            const float4 gj1 = *(const float4*)&Ws[buf][tj + 16][d4];
            #pragma unroll
            for (int r = 0; r < 4; r++) {
                const float4 gi = *(const float4*)&Hs[buf][ti * 4 + r][d4];
                acc[r][0] += gi.x * gj0.x; acc[r][0] += gi.y * gj0.y;
                acc[r][0] += gi.z * gj0.z; acc[r][0] += gi.w * gj0.w;
                acc[r][1] += gi.x * gj1.x; acc[r][1] += gi.y * gj1.y;
                acc[r][1] += gi.z * gj1.z; acc[r][1] += gi.w * gj1.w;
            }
        }
        __syncthreads();

        if (c < 15) {
            #pragma unroll
            for (int p = 0; p < 4; p++) {
                const int e  = tid + p * 128;
                const int rr = e >> 4;
                const int cc = (e & 15) * 4;
                *(float4*)&Hs[buf ^ 1][rr][cc] = hreg[p];
                *(float4*)&Ws[buf ^ 1][rr][cc] = wreg[p];
            }
            __syncthreads();
        }
    }

    // Write G + per-row squared norm (reduce over the 16 tj lanes).
    #pragma unroll
    for (int r = 0; r < 4; r++) {
        const int row = r0 + ti * 4 + r;
        g_G[(size_t)row * KDIM + tj]      = acc[r][0];
        g_G[(size_t)row * KDIM + tj + 16] = acc[r][1];
        float sq = acc[r][0] * acc[r][0] + acc[r][1] * acc[r][1];
        sq += __shfl_xor_sync(0xffffffffu, sq, 1);
        sq += __shfl_xor_sync(0xffffffffu, sq, 2);
        sq += __shfl_xor_sync(0xffffffffu, sq, 4);
        sq += __shfl_xor_sync(0xffffffffu, sq, 8);
        if (tj == 0) g_Gsq[row] = sq;
    }
}

// ---------------------------------------------------------------------------
// Kernel 2: 128(i) x 64(j) tile of
//   clamp(alpha*B_prev - beta*max(|G_i-G_j|^2, 0), -10, 10)
// Gram in packed f32x2 (row-pair accumulators); fused packed epilogue with
// the relu fold: val = min(alpha*b, fma(-beta, raw, alpha*b)).
// ---------------------------------------------------------------------------
__global__ void __launch_bounds__(256) k2_bias(
    const float* __restrict__ Bprev,
    const float* __restrict__ alpha_p,
    const float* __restrict__ beta_p,
    float* __restrict__ out)
{
    __shared__ float Gis[KDIM][132];  // k-major, i in [0,128)
    __shared__ float Gjs[KDIM][68];   // k-major, j in [0,64)
    __shared__ float sqi[128];
    __shared__ float sqj[64];

    const int b   = blockIdx.z;
    const int i0  = blockIdx.y * 128;
    const int j0  = blockIdx.x * 64;
    const int gi0 = b * NSEQ + i0;
    const int gj0 = b * NSEQ + j0;
    const int tid = threadIdx.x;

    const float alpha = *alpha_p;
    const float beta  = *beta_p;

    #pragma unroll
    for (int e = tid; e < 128 * KDIM; e += 256) {
        const int i = e >> 5;
        const int k = e & 31;
        Gis[k][i] = g_G[(size_t)(gi0 + i) * KDIM + k];
    }
    #pragma unroll
    for (int e = tid; e < 64 * KDIM; e += 256) {
        const int j = e >> 5;
        const int k = e & 31;
        Gjs[k][j] = g_G[(size_t)(gj0 + j) * KDIM + k];
    }
    if (tid < 128) sqi[tid] = g_Gsq[gi0 + tid];
    if (tid < 64)  sqj[tid] = g_Gsq[gj0 + tid];
    __syncthreads();

    const int ti = tid >> 4;          // 0..15
    const int tj = tid & 15;          // 0..15
    const int ib = ti * 8;
    const int jb = tj * 4;

    // Packed accumulators: accp[ip][jj] holds rows (ib+2ip, ib+2ip+1), col jb+jj.
    unsigned long long accp[4][4];
    const unsigned long long zero2 = 0ull;
    #pragma unroll
    for (int ip = 0; ip < 4; ip++)
        #pragma unroll
        for (int jj = 0; jj < 4; jj++)
            accp[ip][jj] = zero2;

    #pragma unroll 8
    for (int k = 0; k < KDIM; k++) {
        F4U gia, gib;
        gia.f = *(const float4*)&Gis[k][ib];      // pairs (i0,i1),(i2,i3)
        gib.f = *(const float4*)&Gis[k][ib + 4];  // pairs (i4,i5),(i6,i7)
        const float4 gj = *(const float4*)&Gjs[k][jb];
        const unsigned long long gj0 = pk2(gj.x, gj.x);
        const unsigned long long gj1 = pk2(gj.y, gj.y);
        const unsigned long long gj2 = pk2(gj.z, gj.z);
        const unsigned long long gj3 = pk2(gj.w, gj.w);

        accp[0][0] = fma2(gia.u[0], gj0, accp[0][0]);
        accp[0][1] = fma2(gia.u[0], gj1, accp[0][1]);
        accp[0][2] = fma2(gia.u[0], gj2, accp[0][2]);
        accp[0][3] = fma2(gia.u[0], gj3, accp[0][3]);
        accp[1][0] = fma2(gia.u[1], gj0, accp[1][0]);
        accp[1][1] = fma2(gia.u[1], gj1, accp[1][1]);
        accp[1][2] = fma2(gia.u[1], gj2, accp[1][2]);
        accp[1][3] = fma2(gia.u[1], gj3, accp[1][3]);
        accp[2][0] = fma2(gib.u[0], gj0, accp[2][0]);
        accp[2][1] = fma2(gib.u[0], gj1, accp[2][1]);
        accp[2][2] = fma2(gib.u[0], gj2, accp[2][2]);
        accp[2][3] = fma2(gib.u[0], gj3, accp[2][3]);
        accp[3][0] = fma2(gib.u[1], gj0, accp[3][0]);
        accp[3][1] = fma2(gib.u[1], gj1, accp[3][1]);
        accp[3][2] = fma2(gib.u[1], gj2, accp[3][2]);
        accp[3][3] = fma2(gib.u[1], gj3, accp[3][3]);
    }

    // Epilogue.  raw = si + sj - 2*acc ;  ab = alpha*b ;
    // result = clamp(min(ab, fma(-beta, raw, ab)), -10, 10)
    const unsigned long long alpha2   = pk2(alpha, alpha);
    const unsigned long long negbeta2 = pk2(-beta, -beta);
    const unsigned long long negtwo2  = pk2(-2.0f, -2.0f);

    unsigned long long sj2[4];
    #pragma unroll
    for (int jj = 0; jj < 4; jj++) {
        const float s = sqj[jb + jj];
        sj2[jj] = pk2(s, s);
    }

    const size_t base = ((size_t)b * NSEQ + (i0 + ib)) * NSEQ + (j0 + jb);

    #pragma unroll
    for (int ip = 0; ip < 4; ip++) {
        const int rl = 2 * ip;
        const unsigned long long si2 = pk2(sqi[ib + rl], sqi[ib + rl + 1]);

        F4U bvl, bvh;
        bvl.f = *(const float4*)(Bprev + base + (size_t)rl * NSEQ);
        bvh.f = *(const float4*)(Bprev + base + (size_t)(rl + 1) * NSEQ);

        float ol[4], oh[4];
        #pragma unroll
        for (int jj = 0; jj < 4; jj++) {
            const unsigned long long sij2 = add2(si2, sj2[jj]);
            const unsigned long long raw2 = fma2(negtwo2, accp[ip][jj], sij2);
            const unsigned long long bp2  = pk2(bvl.s[jj], bvh.s[jj]);
            const unsigned long long ab2  = mul2(alpha2, bp2);
            const unsigned long long t2   = fma2(negbeta2, raw2, ab2);
            float abl, abh, tl, th;
            unpk2(ab2, abl, abh);
            unpk2(t2, tl, th);
            float vl = fminf(abl, tl);
            float vh = fminf(abh, th);
            ol[jj] = fminf(fmaxf(vl, -CLAMP_V), CLAMP_V);
            oh[jj] = fminf(fmaxf(vh, -CLAMP_V), CLAMP_V);
        }
        F4U rl4, rh4;
        rl4.s[0] = ol[0]; rl4.s[1] = ol[1]; rl4.s[2] = ol[2]; rl4.s[3] = ol[3];
        rh4.s[0] = oh[0]; rh4.s[1] = oh[1]; rh4.s[2] = oh[2]; rh4.s[3] = oh[3];
        *(float4*)(out + base + (size_t)rl * NSEQ)       = rl4.f;
        *(float4*)(out + base + (size_t)(rl + 1) * NSEQ) = rh4.f;
    }
}

// ---------------------------------------------------------------------------
extern "C" void kernel_launch(void* const* d_in, const int* in_sizes, int n_in,
                              void* d_out, int out_size)
{
    const float* H     = (const float*)d_in[0];
    const float* Bprev = (const float*)d_in[1];
    const float* W     = (const float*)d_in[2];
    const float* alpha = (const float*)d_in[3];
    const float* beta  = (const float*)d_in[4];
    float* out = (float*)d_out;

    k1_proj<<<ROWS / 32, 128>>>(H, W);

    dim3 g2(NSEQ / 64, NSEQ / 128, BATCH);
    k2_bias<<<g2, 256>>>(Bprev, alpha, beta, out);
}